// round 6
// baseline (speedup 1.0000x reference)
#include <cuda_runtime.h>
#include <stdint.h>

// NaiveVisCache: per-ray cube-face select + morton3d index + cache gather + threshold.
// d_in[0] = norm_ray_origins (B,3) f32, d_in[1] = viewdirs (B,3) f32,
// d_in[2] = cache (128^3,6) int32. Output: B f32 (0.0/1.0).
//
// KEY semantic detail (measured, q=0.1391 matches (ln2-1/2)/(2ln2)): the
// reference's division v/inf_norm is lowered as v * fl_rn(1/inf_norm)
// (reciprocal-multiply). x*fl(1/x) rounds to 1-ulp for ~13.9% of inputs, so
// no quadrant condition fires and face falls back to 0. We replicate with
// __frcp_rn + __fmul_rn.

#define MIDPOINT 128

__device__ __forceinline__ unsigned expand_bits(unsigned v) {
    v = (v | (v << 16)) & 0x030000FFu;
    v = (v | (v << 8))  & 0x0300F00Fu;
    v = (v | (v << 4))  & 0x030C30C3u;
    v = (v | (v << 2))  & 0x09249249u;
    return v;
}

__global__ void __launch_bounds__(256)
vis_cache_kernel(const float4* __restrict__ org4,
                 const float4* __restrict__ dir4,
                 const int*    __restrict__ cache,
                 float4*       __restrict__ out4,
                 int n_quads)  // n_rays / 4
{
    int t = blockIdx.x * blockDim.x + threadIdx.x;
    if (t >= n_quads) return;

    // 4 rays = 12 floats = 3 float4 loads per array (fully coalesced)
    float4 oa = org4[3 * t + 0];
    float4 ob = org4[3 * t + 1];
    float4 oc = org4[3 * t + 2];
    float4 va = dir4[3 * t + 0];
    float4 vb = dir4[3 * t + 1];
    float4 vc = dir4[3 * t + 2];

    float of[12] = {oa.x, oa.y, oa.z, oa.w, ob.x, ob.y, ob.z, ob.w, oc.x, oc.y, oc.z, oc.w};
    float vf[12] = {va.x, va.y, va.z, va.w, vb.x, vb.y, vb.z, vb.w, vc.x, vc.y, vc.z, vc.w};

    // Phase 1: morton indices (exact-integer path; overlaps the rcp chain below).
    unsigned base[4];
    #pragma unroll
    for (int j = 0; j < 4; j++) {
        // clip((o/2 + 0.5) * 128, 0, 127), truncate. All power-of-2 exact ops.
        float cx = fminf(fmaxf((of[3 * j + 0] * 0.5f + 0.5f) * 128.0f, 0.0f), 127.0f);
        float cy = fminf(fmaxf((of[3 * j + 1] * 0.5f + 0.5f) * 128.0f, 0.0f), 127.0f);
        float cz = fminf(fmaxf((of[3 * j + 2] * 0.5f + 0.5f) * 128.0f, 0.0f), 127.0f);

        unsigned idx = expand_bits((unsigned)(int)cx)
                     | (expand_bits((unsigned)(int)cy) << 1)
                     | (expand_bits((unsigned)(int)cz) << 2);
        base[j] = idx * 6u;
    }

    // Phase 2: face select — reciprocal-multiply to bit-match the reference.
    float res[4];
    #pragma unroll
    for (int j = 0; j < 4; j++) {
        float a = vf[3 * j + 0];
        float b = vf[3 * j + 1];
        float c = vf[3 * j + 2];

        float n = fmaxf(fabsf(a), fmaxf(fabsf(b), fabsf(c)));
        float r  = __frcp_rn(n);       // correctly-rounded 1/n
        float sa = __fmul_rn(a, r);    // RN multiply — NOT a fused divide
        float sb = __fmul_rn(b, r);
        float sc = __fmul_rn(c, r);

        // jnp.where chain: LAST true condition wins; may fire nothing -> face 0.
        int face = 0;
        if (sa >=  1.0f) face = 0;
        if (sa <= -1.0f) face = 1;
        if (sb >=  1.0f) face = 2;
        if (sb <= -1.0f) face = 3;
        if (sc >=  1.0f) face = 4;
        if (sc <= -1.0f) face = 5;

        int val = __ldg(&cache[base[j] + (unsigned)face]);
        res[j] = (val > MIDPOINT) ? 1.0f : 0.0f;
    }

    out4[t] = make_float4(res[0], res[1], res[2], res[3]);
}

extern "C" void kernel_launch(void* const* d_in, const int* in_sizes, int n_in,
                              void* d_out, int out_size)
{
    const float4* org4  = (const float4*)d_in[0];
    const float4* dir4  = (const float4*)d_in[1];
    const int*    cache = (const int*)d_in[2];
    float4*       out4  = (float4*)d_out;

    int n_rays  = in_sizes[0] / 3;   // 4194304
    int n_quads = n_rays / 4;        // 1048576

    int threads = 256;
    int blocks  = (n_quads + threads - 1) / threads;
    vis_cache_kernel<<<blocks, threads>>>(org4, dir4, cache, out4, n_quads);
}

// round 7
// speedup vs baseline: 1.0491x; 1.0491x over previous
#include <cuda_runtime.h>
#include <stdint.h>

// NaiveVisCache: per-ray cube-face select + morton3d index + cache gather + threshold.
// d_in[0] = norm_ray_origins (B,3) f32, d_in[1] = viewdirs (B,3) f32,
// d_in[2] = cache (128^3,6) int32. Output: B f32 (0.0/1.0).
//
// Semantics (verified rel_err=0.0 in R6): reference lowers v/inf_norm as
// v * fl_rn(1/inf_norm) -> replicate with __frcp_rn + __fmul_rn; where-chain
// falls back to face 0 when x*fl(1/x) rounds below 1.0 (~13.9% of rays).
//
// Perf strategy: streams use __ldcs (evict-first) and __stcs so the 48MB cache
// table stays resident in L2 across graph replays; 8 rays/thread batches 8
// independent gathers for MLP.

#define MIDPOINT 128

__device__ __forceinline__ unsigned expand_bits(unsigned v) {
    v = (v | (v << 16)) & 0x030000FFu;
    v = (v | (v << 8))  & 0x0300F00Fu;
    v = (v | (v << 4))  & 0x030C30C3u;
    v = (v | (v << 2))  & 0x09249249u;
    return v;
}

__global__ void __launch_bounds__(256)
vis_cache_kernel(const float4* __restrict__ org4,
                 const float4* __restrict__ dir4,
                 const int*    __restrict__ cache,
                 float4*       __restrict__ out4,
                 int n_oct)  // n_rays / 8
{
    int t = blockIdx.x * blockDim.x + threadIdx.x;
    if (t >= n_oct) return;

    // 8 rays = 24 floats = 6 float4 loads per array. Evict-first: pure stream.
    float4 o[6], v[6];
    #pragma unroll
    for (int k = 0; k < 6; k++) o[k] = __ldcs(&org4[6 * t + k]);
    #pragma unroll
    for (int k = 0; k < 6; k++) v[k] = __ldcs(&dir4[6 * t + k]);

    const float* of = reinterpret_cast<const float*>(o);  // fully unrolled -> registers
    const float* vf = reinterpret_cast<const float*>(v);

    // Phase 1: morton base indices (exact-integer path).
    unsigned base[8];
    #pragma unroll
    for (int j = 0; j < 8; j++) {
        float cx = fminf(fmaxf((of[3 * j + 0] * 0.5f + 0.5f) * 128.0f, 0.0f), 127.0f);
        float cy = fminf(fmaxf((of[3 * j + 1] * 0.5f + 0.5f) * 128.0f, 0.0f), 127.0f);
        float cz = fminf(fmaxf((of[3 * j + 2] * 0.5f + 0.5f) * 128.0f, 0.0f), 127.0f);

        unsigned idx = expand_bits((unsigned)(int)cx)
                     | (expand_bits((unsigned)(int)cy) << 1)
                     | (expand_bits((unsigned)(int)cz) << 2);
        base[j] = idx * 6u;
    }

    // Phase 2: face select (reciprocal-multiply, bit-matching the reference).
    unsigned addr[8];
    #pragma unroll
    for (int j = 0; j < 8; j++) {
        float a = vf[3 * j + 0];
        float b = vf[3 * j + 1];
        float c = vf[3 * j + 2];

        float n = fmaxf(fabsf(a), fmaxf(fabsf(b), fabsf(c)));
        float r  = __frcp_rn(n);
        float sa = __fmul_rn(a, r);
        float sb = __fmul_rn(b, r);
        float sc = __fmul_rn(c, r);

        int face = 0;
        if (sa >=  1.0f) face = 0;
        if (sa <= -1.0f) face = 1;
        if (sb >=  1.0f) face = 2;
        if (sb <= -1.0f) face = 3;
        if (sc >=  1.0f) face = 4;
        if (sc <= -1.0f) face = 5;

        addr[j] = base[j] + (unsigned)face;
    }

    // Phase 3: 8 independent gathers in flight (evict-normal -> table owns L2).
    int val[8];
    #pragma unroll
    for (int j = 0; j < 8; j++) val[j] = __ldg(&cache[addr[j]]);

    float4 r0 = make_float4(val[0] > MIDPOINT ? 1.0f : 0.0f,
                            val[1] > MIDPOINT ? 1.0f : 0.0f,
                            val[2] > MIDPOINT ? 1.0f : 0.0f,
                            val[3] > MIDPOINT ? 1.0f : 0.0f);
    float4 r1 = make_float4(val[4] > MIDPOINT ? 1.0f : 0.0f,
                            val[5] > MIDPOINT ? 1.0f : 0.0f,
                            val[6] > MIDPOINT ? 1.0f : 0.0f,
                            val[7] > MIDPOINT ? 1.0f : 0.0f);

    __stcs(&out4[2 * t + 0], r0);   // output is never re-read: stream it out
    __stcs(&out4[2 * t + 1], r1);
}

extern "C" void kernel_launch(void* const* d_in, const int* in_sizes, int n_in,
                              void* d_out, int out_size)
{
    const float4* org4  = (const float4*)d_in[0];
    const float4* dir4  = (const float4*)d_in[1];
    const int*    cache = (const int*)d_in[2];
    float4*       out4  = (float4*)d_out;

    int n_rays = in_sizes[0] / 3;   // 4194304
    int n_oct  = n_rays / 8;        // 524288

    int threads = 256;
    int blocks  = (n_oct + threads - 1) / threads;
    vis_cache_kernel<<<blocks, threads>>>(org4, dir4, cache, out4, n_oct);
}